// round 5
// baseline (speedup 1.0000x reference)
#include <cuda_runtime.h>
#include <cuda_bf16.h>
#include <cstdint>
#include <cstddef>

#define NTHREADS 256
#define GRID     148
#define TB       128
#define NTILES   1024   // 131072 / 128

// ---------------- smem layout (bytes) ----------------
// padded K-major bf16 tiles: row stride = K*2 + 16 bytes (conflict-free ldmatrix)
#define ST32B  80     // K=32 rows: 32*2+16
#define ST128B 272    // K=128 rows: 128*2+16
#define S_XH   0                    // x hi  [128 rows x 80B]
#define S_XL   10240
#define S_W0H  20480                // W0 [128 x 80B]
#define S_W0L  30720
#define S_W1H  40960                // W1 [128 x 272B]
#define S_W1L  75776
#define S_W2H  110592               // W2 [16 x 272B]  (rows >= OUT zero)
#define S_W2L  114944
#define S_B0   119296               // 128 f32
#define S_B1   119808
#define S_B2   120320               // 16 f32
#define S_OUT  120448               // [128 rows x 16 f32] staging
#define SMEM_TOTAL 128640

// ---------------- PTX helpers ----------------
__device__ __forceinline__ uint32_t cvta_s(const void* p) {
    uint32_t a;
    asm("{ .reg .u64 t; cvta.to.shared.u64 t, %1; cvt.u32.u64 %0, t; }"
        : "=r"(a) : "l"(p));
    return a;
}
__device__ __forceinline__ void ldsm4(uint32_t* r, uint32_t addr) {
    asm volatile("ldmatrix.sync.aligned.m8n8.x4.shared.b16 {%0,%1,%2,%3}, [%4];"
                 : "=r"(r[0]), "=r"(r[1]), "=r"(r[2]), "=r"(r[3]) : "r"(addr));
}
__device__ __forceinline__ void mma16816(float* d, const uint32_t* a,
                                         uint32_t b0, uint32_t b1) {
    asm volatile(
        "mma.sync.aligned.m16n8k16.row.col.f32.bf16.bf16.f32 "
        "{%0,%1,%2,%3}, {%4,%5,%6,%7}, {%8,%9}, {%0,%1,%2,%3};"
        : "+f"(d[0]), "+f"(d[1]), "+f"(d[2]), "+f"(d[3])
        : "r"(a[0]), "r"(a[1]), "r"(a[2]), "r"(a[3]), "r"(b0), "r"(b1));
}
__device__ __forceinline__ uint32_t pkbf(float lo, float hi) {  // low half = lo
    uint32_t r;
    asm("cvt.rn.bf16x2.f32 %0, %1, %2;" : "=r"(r) : "f"(hi), "f"(lo));
    return r;
}
__device__ __forceinline__ float bf_lo(uint32_t u) { return __uint_as_float(u << 16); }
__device__ __forceinline__ float bf_hi(uint32_t u) { return __uint_as_float(u & 0xFFFF0000u); }

// ---------------- 3x3 expm (validated round 1/2) ----------------
__device__ __forceinline__ void mm3(const float* A, const float* B, float* C) {
#pragma unroll
    for (int i = 0; i < 3; i++)
#pragma unroll
        for (int j = 0; j < 3; j++)
            C[3 * i + j] = fmaf(A[3 * i + 0], B[0 + j],
                           fmaf(A[3 * i + 1], B[3 + j],
                                A[3 * i + 2] * B[6 + j]));
}
__device__ void expm3(const float* A, float* E) {
    float n = 0.f;
#pragma unroll
    for (int i = 0; i < 3; i++) {
        float rs = fabsf(A[3 * i]) + fabsf(A[3 * i + 1]) + fabsf(A[3 * i + 2]);
        n = fmaxf(n, rs);
    }
    int s = 0;
    if (n > 0.5f) { s = (int)ceilf(log2f(n)) + 1; if (s < 0) s = 0; }
    float sc = ldexpf(1.f, -s);
    float As[9], T[9], M[9];
#pragma unroll
    for (int i = 0; i < 9; i++) {
        As[i] = A[i] * sc;
        T[i] = (i == 0 || i == 4 || i == 8) ? 1.f : 0.f;
    }
#pragma unroll
    for (int k = 10; k >= 1; --k) {
        mm3(As, T, M);
        float inv = 1.f / (float)k;
#pragma unroll
        for (int i = 0; i < 9; i++)
            T[i] = ((i == 0 || i == 4 || i == 8) ? 1.f : 0.f) + M[i] * inv;
    }
    for (int q = 0; q < s; q++) {
        mm3(T, T, M);
#pragma unroll
        for (int i = 0; i < 9; i++) T[i] = M[i];
    }
#pragma unroll
    for (int i = 0; i < 9; i++) E[i] = T[i];
}

// ---------------- split fp32 -> bf16 hi/lo, 4 consecutive elems ----------
__device__ __forceinline__ void split_store4(char* sm, uint32_t off_hi, uint32_t off_lo,
                                             float4 v) {
    uint32_t h01 = pkbf(v.x, v.y);
    uint32_t h23 = pkbf(v.z, v.w);
    float l0 = v.x - bf_lo(h01), l1 = v.y - bf_hi(h01);
    float l2 = v.z - bf_lo(h23), l3 = v.w - bf_hi(h23);
    *(uint2*)(sm + off_hi) = make_uint2(h01, h23);
    *(uint2*)(sm + off_lo) = make_uint2(pkbf(l0, l1), pkbf(l2, l3));
}

// ---------------- weight conversion: fp32 [R x C] -> padded split bf16 ---
__device__ void conv_w(const float* __restrict__ src, int R, int C, int RP,
                       int strideB, char* sm, uint32_t dhi, uint32_t dlo, int tid) {
    const int c4n = C / 4;
    const int tot = RP * c4n;
    for (int i = tid; i < tot; i += NTHREADS) {
        int row = i / c4n, c4 = i - row * c4n;
        float4 v = (row < R) ? *(const float4*)(src + (size_t)row * C + c4 * 4)
                             : make_float4(0.f, 0.f, 0.f, 0.f);
        uint32_t o = (uint32_t)(row * strideB + c4 * 8);
        split_store4(sm, dhi + o, dlo + o, v);
    }
}

// ---------------- GEMM layer: D[NT16*8] += (Ah+Al) x (Bh+Bl) -------------
template <int KT, int NT16, int STRIDEB>
__device__ __forceinline__ void gemm(uint32_t bh_base, uint32_t bl_base,
                                     const uint32_t* ah, const uint32_t* al,
                                     float* d, int n_in, int k_in) {
#pragma unroll
    for (int nt = 0; nt < NT16; nt++) {
#pragma unroll
        for (int kt = 0; kt < KT; kt++) {
            uint32_t off = (uint32_t)((nt * 16 + n_in) * STRIDEB + kt * 32 + k_in * 2);
            uint32_t bh[4], bl[4];
            ldsm4(bh, bh_base + off);
            ldsm4(bl, bl_base + off);
            float* d0 = d + nt * 8;
            float* d1 = d + nt * 8 + 4;
            mma16816(d0, ah + kt * 4, bh[0], bh[1]);
            mma16816(d1, ah + kt * 4, bh[2], bh[3]);
            mma16816(d0, al + kt * 4, bh[0], bh[1]);
            mma16816(d1, al + kt * 4, bh[2], bh[3]);
            mma16816(d0, ah + kt * 4, bl[0], bl[1]);
            mma16816(d1, ah + kt * 4, bl[2], bl[3]);
        }
    }
}

// ---------------- epilogue: D[64] + bias -> relu -> split A frags --------
__device__ __forceinline__ void epi128(const float* d, const char* sm, uint32_t bias_off,
                                       uint32_t* ah, uint32_t* al, int lane) {
    const int cb = (lane & 3) * 2;
#pragma unroll
    for (int tj = 0; tj < 16; tj++) {
        float2 bb = *(const float2*)(sm + bias_off + (tj * 8 + cb) * 4);
        float v0 = fmaxf(d[tj * 4 + 0] + bb.x, 0.f);
        float v1 = fmaxf(d[tj * 4 + 1] + bb.y, 0.f);
        float v2 = fmaxf(d[tj * 4 + 2] + bb.x, 0.f);
        float v3 = fmaxf(d[tj * 4 + 3] + bb.y, 0.f);
        uint32_t h01 = pkbf(v0, v1);
        uint32_t h23 = pkbf(v2, v3);
        float l0 = v0 - bf_lo(h01), l1 = v1 - bf_hi(h01);
        float l2 = v2 - bf_lo(h23), l3 = v3 - bf_hi(h23);
        const int idx = (tj >> 1) * 4 + (tj & 1) * 2;
        ah[idx + 0] = h01;
        ah[idx + 1] = h23;
        al[idx + 0] = pkbf(l0, l1);
        al[idx + 1] = pkbf(l2, l3);
    }
}

// ---------------- main fused kernel ----------------
__global__ __launch_bounds__(NTHREADS, 1)
void fused_kernel(const float* __restrict__ y,
                  const float* __restrict__ ow0, const float* __restrict__ ob0,
                  const float* __restrict__ ow1, const float* __restrict__ ob1,
                  const float* __restrict__ ow2, const float* __restrict__ ob2,
                  const float* __restrict__ tw0, const float* __restrict__ tb0,
                  const float* __restrict__ tw1, const float* __restrict__ tb1,
                  const float* __restrict__ tw2, const float* __restrict__ tb2,
                  float* __restrict__ out) {
    extern __shared__ char sm[];
    const uint32_t smb = cvta_s(sm);
    const int tid = threadIdx.x;
    const int warp = tid >> 5;
    const int lane = tid & 31;

    // ldmatrix lane geometry
    const int lt = lane >> 3, lr = lane & 7;
    const int b_n = (lt >> 1) * 8 + lr;   // B x4: n row within n16 group
    const int b_k = (lt & 1) * 8;         // B x4: k offset within k16
    const int a_m = (lt & 1) * 8 + lr;    // A x4: m row within m16
    const int a_k = (lt >> 1) * 8;        // A x4: k offset within k16

    for (int br = 0; br < 2; br++) {
        const float* w0 = br ? tw0 : ow0;
        const float* w1 = br ? tw1 : ow1;
        const float* w2 = br ? tw2 : ow2;
        const float* b0 = br ? tb0 : ob0;
        const float* b1 = br ? tb1 : ob1;
        const float* b2 = br ? tb2 : ob2;
        const int coloff = br ? 32 : 0;
        const int OUTN = br ? 3 : 9;

        __syncthreads();  // previous branch fully done before weight overwrite
        conv_w(w0, 128, 32, 128, ST32B, sm, S_W0H, S_W0L, tid);
        conv_w(w1, 128, 128, 128, ST128B, sm, S_W1H, S_W1L, tid);
        conv_w(w2, OUTN, 128, 16, ST128B, sm, S_W2H, S_W2L, tid);
        if (tid < 128) ((float*)(sm + S_B0))[tid] = b0[tid];
        else if (tid < 256) ((float*)(sm + S_B1))[tid - 128] = b1[tid - 128];
        if (tid < 16) ((float*)(sm + S_B2))[tid] = (tid < OUTN) ? b2[tid] : 0.f;
        __syncthreads();

        for (int t = blockIdx.x; t < NTILES; t += GRID) {
            const int r0 = t * TB;

            // ---- stage x tile: [128 x 32] split bf16, padded rows ----
#pragma unroll
            for (int pass = 0; pass < 4; pass++) {
                int i = tid + pass * NTHREADS;        // 1024 float4s
                int row = i >> 3, c4 = i & 7;
                float4 v = *(const float4*)(y + (size_t)(r0 + row) * 64 + coloff + c4 * 4);
                uint32_t o = (uint32_t)(row * ST32B + c4 * 8);
                split_store4(sm, S_XH + o, S_XL + o, v);
            }
            __syncthreads();

            // ---- load x A-fragments ----
            uint32_t axh[8], axl[8];
#pragma unroll
            for (int kt = 0; kt < 2; kt++) {
                uint32_t o = (uint32_t)((warp * 16 + a_m) * ST32B + (kt * 16 + a_k) * 2);
                ldsm4(axh + kt * 4, smb + S_XH + o);
                ldsm4(axl + kt * 4, smb + S_XL + o);
            }

            // ---- layer 1: [16 x 32] x W0^T -> D[16 x 128] ----
            float d[64];
#pragma unroll
            for (int i = 0; i < 64; i++) d[i] = 0.f;
            gemm<2, 8, ST32B>(smb + S_W0H, smb + S_W0L, axh, axl, d, b_n, b_k);

            uint32_t acth[32], actl[32];
            epi128(d, sm, S_B0, acth, actl, lane);

            // ---- layer 2: [16 x 128] x W1^T -> D[16 x 128] ----
#pragma unroll
            for (int i = 0; i < 64; i++) d[i] = 0.f;
            gemm<8, 8, ST128B>(smb + S_W1H, smb + S_W1L, acth, actl, d, b_n, b_k);
            epi128(d, sm, S_B1, acth, actl, lane);

            // ---- layer 3: [16 x 128] x W2^T -> D3[16 x 16] ----
            float d3[8];
#pragma unroll
            for (int i = 0; i < 8; i++) d3[i] = 0.f;
            gemm<8, 1, ST128B>(smb + S_W2H, smb + S_W2L, acth, actl, d3, b_n, b_k);

            // ---- stage D3 to smem [row][16] ----
            {
                char* ob = sm + S_OUT + (size_t)(warp * 16) * 64;
                const int rlo = lane >> 2;
                const int c = (lane & 3) * 2;
#pragma unroll
                for (int tj = 0; tj < 2; tj++) {
                    *(float2*)(ob + rlo * 64 + (tj * 8 + c) * 4) =
                        make_float2(d3[tj * 4 + 0], d3[tj * 4 + 1]);
                    *(float2*)(ob + (rlo + 8) * 64 + (tj * 8 + c) * 4) =
                        make_float2(d3[tj * 4 + 2], d3[tj * 4 + 3]);
                }
            }
            __syncthreads();

            // ---- bias + expm + write ----
            if (tid < TB) {
                const float* orow_s = (const float*)(sm + S_OUT) + tid * 16;
                const float* b2s = (const float*)(sm + S_B2);
                float* og = out + (size_t)(r0 + tid) * 12 + (br ? 9 : 0);
                if (br == 0) {
                    float om[9], E[9];
#pragma unroll
                    for (int o = 0; o < 9; o++) om[o] = orow_s[o] + b2s[o];
                    expm3(om, E);
#pragma unroll
                    for (int o = 0; o < 9; o++) og[o] = E[o];
                } else {
#pragma unroll
                    for (int o = 0; o < 3; o++) og[o] = orow_s[o] + b2s[o];
                }
            }
            __syncthreads();
        }
    }
}

// ---------------- launch ----------------
extern "C" void kernel_launch(void* const* d_in, const int* in_sizes, int n_in,
                              void* d_out, int out_size) {
    const float* y   = (const float*)d_in[0];
    const float* ow0 = (const float*)d_in[1];
    const float* ob0 = (const float*)d_in[2];
    const float* ow1 = (const float*)d_in[3];
    const float* ob1 = (const float*)d_in[4];
    const float* ow2 = (const float*)d_in[5];
    const float* ob2 = (const float*)d_in[6];
    const float* tw0 = (const float*)d_in[7];
    const float* tb0 = (const float*)d_in[8];
    const float* tw1 = (const float*)d_in[9];
    const float* tb1 = (const float*)d_in[10];
    const float* tw2 = (const float*)d_in[11];
    const float* tb2 = (const float*)d_in[12];
    float* out = (float*)d_out;

    cudaFuncSetAttribute(fused_kernel,
                         cudaFuncAttributeMaxDynamicSharedMemorySize, SMEM_TOTAL);
    fused_kernel<<<GRID, NTHREADS, SMEM_TOTAL>>>(
        y, ow0, ob0, ow1, ob1, ow2, ob2, tw0, tb0, tw1, tb1, tw2, tb2, out);
}

// round 6
// speedup vs baseline: 1.0065x; 1.0065x over previous
#include <cuda_runtime.h>
#include <cuda_bf16.h>
#include <cstdint>
#include <cstddef>

#define NTHREADS 256
#define GRID     148
#define TB       128
#define NTILES   1024   // 131072 / 128

// ---------------- smem layout (bytes) ----------------
// padded K-major bf16 tiles: row stride = K*2 + 16 bytes (conflict-free ldmatrix)
#define ST32B  80     // K=32 rows: 32*2+16
#define ST128B 272    // K=128 rows: 128*2+16
#define S_XH   0                    // x hi  [128 rows x 80B]
#define S_XL   10240
#define S_W0H  20480                // W0 [128 x 80B]
#define S_W0L  30720
#define S_W1H  40960                // W1 [128 x 272B]
#define S_W1L  75776
#define S_W2H  110592               // W2 [16 x 272B]  (rows >= OUT zero)
#define S_W2L  114944
#define S_B0   119296               // 128 f32
#define S_B1   119808
#define S_B2   120320               // 16 f32
#define S_OUT  120448               // [128 rows x 16 f32] staging
#define SMEM_TOTAL 128640

// ---------------- PTX helpers ----------------
__device__ __forceinline__ uint32_t cvta_s(const void* p) {
    uint32_t a;
    asm("{ .reg .u64 t; cvta.to.shared.u64 t, %1; cvt.u32.u64 %0, t; }"
        : "=r"(a) : "l"(p));
    return a;
}
__device__ __forceinline__ void ldsm4(uint32_t* r, uint32_t addr) {
    asm volatile("ldmatrix.sync.aligned.m8n8.x4.shared.b16 {%0,%1,%2,%3}, [%4];"
                 : "=r"(r[0]), "=r"(r[1]), "=r"(r[2]), "=r"(r[3]) : "r"(addr));
}
__device__ __forceinline__ void mma16816(float* d, const uint32_t* a,
                                         uint32_t b0, uint32_t b1) {
    asm volatile(
        "mma.sync.aligned.m16n8k16.row.col.f32.bf16.bf16.f32 "
        "{%0,%1,%2,%3}, {%4,%5,%6,%7}, {%8,%9}, {%0,%1,%2,%3};"
        : "+f"(d[0]), "+f"(d[1]), "+f"(d[2]), "+f"(d[3])
        : "r"(a[0]), "r"(a[1]), "r"(a[2]), "r"(a[3]), "r"(b0), "r"(b1));
}
__device__ __forceinline__ uint32_t pkbf(float lo, float hi) {  // low half = lo
    uint32_t r;
    asm("cvt.rn.bf16x2.f32 %0, %1, %2;" : "=r"(r) : "f"(hi), "f"(lo));
    return r;
}
__device__ __forceinline__ float bf_lo(uint32_t u) { return __uint_as_float(u << 16); }
__device__ __forceinline__ float bf_hi(uint32_t u) { return __uint_as_float(u & 0xFFFF0000u); }

// ---------------- 3x3 expm (validated round 1/2) ----------------
__device__ __forceinline__ void mm3(const float* A, const float* B, float* C) {
#pragma unroll
    for (int i = 0; i < 3; i++)
#pragma unroll
        for (int j = 0; j < 3; j++)
            C[3 * i + j] = fmaf(A[3 * i + 0], B[0 + j],
                           fmaf(A[3 * i + 1], B[3 + j],
                                A[3 * i + 2] * B[6 + j]));
}
__device__ void expm3(const float* A, float* E) {
    float n = 0.f;
#pragma unroll
    for (int i = 0; i < 3; i++) {
        float rs = fabsf(A[3 * i]) + fabsf(A[3 * i + 1]) + fabsf(A[3 * i + 2]);
        n = fmaxf(n, rs);
    }
    int s = 0;
    if (n > 0.5f) { s = (int)ceilf(log2f(n)) + 1; if (s < 0) s = 0; }
    float sc = ldexpf(1.f, -s);
    float As[9], T[9], M[9];
#pragma unroll
    for (int i = 0; i < 9; i++) {
        As[i] = A[i] * sc;
        T[i] = (i == 0 || i == 4 || i == 8) ? 1.f : 0.f;
    }
#pragma unroll
    for (int k = 10; k >= 1; --k) {
        mm3(As, T, M);
        float inv = 1.f / (float)k;
#pragma unroll
        for (int i = 0; i < 9; i++)
            T[i] = ((i == 0 || i == 4 || i == 8) ? 1.f : 0.f) + M[i] * inv;
    }
    for (int q = 0; q < s; q++) {
        mm3(T, T, M);
#pragma unroll
        for (int i = 0; i < 9; i++) T[i] = M[i];
    }
#pragma unroll
    for (int i = 0; i < 9; i++) E[i] = T[i];
}

// ---------------- split fp32 -> bf16 hi/lo, 4 consecutive elems ----------
__device__ __forceinline__ void split_store4(char* sm, uint32_t off_hi, uint32_t off_lo,
                                             float4 v) {
    uint32_t h01 = pkbf(v.x, v.y);
    uint32_t h23 = pkbf(v.z, v.w);
    float l0 = v.x - bf_lo(h01), l1 = v.y - bf_hi(h01);
    float l2 = v.z - bf_lo(h23), l3 = v.w - bf_hi(h23);
    *(uint2*)(sm + off_hi) = make_uint2(h01, h23);
    *(uint2*)(sm + off_lo) = make_uint2(pkbf(l0, l1), pkbf(l2, l3));
}

// ---------------- weight conversion: fp32 [R x C] -> padded split bf16 ---
__device__ void conv_w(const float* __restrict__ src, int R, int C, int RP,
                       int strideB, char* sm, uint32_t dhi, uint32_t dlo, int tid) {
    const int c4n = C / 4;
    const int tot = RP * c4n;
    for (int i = tid; i < tot; i += NTHREADS) {
        int row = i / c4n, c4 = i - row * c4n;
        float4 v = (row < R) ? *(const float4*)(src + (size_t)row * C + c4 * 4)
                             : make_float4(0.f, 0.f, 0.f, 0.f);
        uint32_t o = (uint32_t)(row * strideB + c4 * 8);
        split_store4(sm, dhi + o, dlo + o, v);
    }
}

// ---------------- GEMM layer: D[NT16*8] += (Ah+Al) x (Bh+Bl) -------------
template <int KT, int NT16, int STRIDEB>
__device__ __forceinline__ void gemm(uint32_t bh_base, uint32_t bl_base,
                                     const uint32_t* ah, const uint32_t* al,
                                     float* d, int n_in, int k_in) {
#pragma unroll
    for (int nt = 0; nt < NT16; nt++) {
#pragma unroll
        for (int kt = 0; kt < KT; kt++) {
            uint32_t off = (uint32_t)((nt * 16 + n_in) * STRIDEB + kt * 32 + k_in * 2);
            uint32_t bh[4], bl[4];
            ldsm4(bh, bh_base + off);
            ldsm4(bl, bl_base + off);
            float* d0 = d + nt * 8;
            float* d1 = d + nt * 8 + 4;
            mma16816(d0, ah + kt * 4, bh[0], bh[1]);
            mma16816(d1, ah + kt * 4, bh[2], bh[3]);
            mma16816(d0, al + kt * 4, bh[0], bh[1]);
            mma16816(d1, al + kt * 4, bh[2], bh[3]);
            mma16816(d0, ah + kt * 4, bl[0], bl[1]);
            mma16816(d1, ah + kt * 4, bl[2], bl[3]);
        }
    }
}

// ---------------- epilogue: D[64] + bias -> relu -> split A frags --------
__device__ __forceinline__ void epi128(const float* d, const char* sm, uint32_t bias_off,
                                       uint32_t* ah, uint32_t* al, int lane) {
    const int cb = (lane & 3) * 2;
#pragma unroll
    for (int tj = 0; tj < 16; tj++) {
        float2 bb = *(const float2*)(sm + bias_off + (tj * 8 + cb) * 4);
        float v0 = fmaxf(d[tj * 4 + 0] + bb.x, 0.f);
        float v1 = fmaxf(d[tj * 4 + 1] + bb.y, 0.f);
        float v2 = fmaxf(d[tj * 4 + 2] + bb.x, 0.f);
        float v3 = fmaxf(d[tj * 4 + 3] + bb.y, 0.f);
        uint32_t h01 = pkbf(v0, v1);
        uint32_t h23 = pkbf(v2, v3);
        float l0 = v0 - bf_lo(h01), l1 = v1 - bf_hi(h01);
        float l2 = v2 - bf_lo(h23), l3 = v3 - bf_hi(h23);
        const int idx = (tj >> 1) * 4 + (tj & 1) * 2;
        ah[idx + 0] = h01;
        ah[idx + 1] = h23;
        al[idx + 0] = pkbf(l0, l1);
        al[idx + 1] = pkbf(l2, l3);
    }
}

// ---------------- main fused kernel ----------------
__global__ __launch_bounds__(NTHREADS, 1)
void fused_kernel(const float* __restrict__ y,
                  const float* __restrict__ ow0, const float* __restrict__ ob0,
                  const float* __restrict__ ow1, const float* __restrict__ ob1,
                  const float* __restrict__ ow2, const float* __restrict__ ob2,
                  const float* __restrict__ tw0, const float* __restrict__ tb0,
                  const float* __restrict__ tw1, const float* __restrict__ tb1,
                  const float* __restrict__ tw2, const float* __restrict__ tb2,
                  float* __restrict__ out) {
    extern __shared__ char sm[];
    const uint32_t smb = cvta_s(sm);
    const int tid = threadIdx.x;
    const int warp = tid >> 5;
    const int lane = tid & 31;

    // ldmatrix lane geometry
    const int lt = lane >> 3, lr = lane & 7;
    const int b_n = (lt >> 1) * 8 + lr;   // B x4: n row within n16 group
    const int b_k = (lt & 1) * 8;         // B x4: k offset within k16
    const int a_m = (lt & 1) * 8 + lr;    // A x4: m row within m16
    const int a_k = (lt >> 1) * 8;        // A x4: k offset within k16

    for (int br = 0; br < 2; br++) {
        const float* w0 = br ? tw0 : ow0;
        const float* w1 = br ? tw1 : ow1;
        const float* w2 = br ? tw2 : ow2;
        const float* b0 = br ? tb0 : ob0;
        const float* b1 = br ? tb1 : ob1;
        const float* b2 = br ? tb2 : ob2;
        const int coloff = br ? 32 : 0;
        const int OUTN = br ? 3 : 9;

        __syncthreads();  // previous branch fully done before weight overwrite
        conv_w(w0, 128, 32, 128, ST32B, sm, S_W0H, S_W0L, tid);
        conv_w(w1, 128, 128, 128, ST128B, sm, S_W1H, S_W1L, tid);
        conv_w(w2, OUTN, 128, 16, ST128B, sm, S_W2H, S_W2L, tid);
        if (tid < 128) ((float*)(sm + S_B0))[tid] = b0[tid];
        else if (tid < 256) ((float*)(sm + S_B1))[tid - 128] = b1[tid - 128];
        if (tid < 16) ((float*)(sm + S_B2))[tid] = (tid < OUTN) ? b2[tid] : 0.f;
        __syncthreads();

        for (int t = blockIdx.x; t < NTILES; t += GRID) {
            const int r0 = t * TB;

            // ---- stage x tile: [128 x 32] split bf16, padded rows ----
#pragma unroll
            for (int pass = 0; pass < 4; pass++) {
                int i = tid + pass * NTHREADS;        // 1024 float4s
                int row = i >> 3, c4 = i & 7;
                float4 v = *(const float4*)(y + (size_t)(r0 + row) * 64 + coloff + c4 * 4);
                uint32_t o = (uint32_t)(row * ST32B + c4 * 8);
                split_store4(sm, S_XH + o, S_XL + o, v);
            }
            __syncthreads();

            // ---- load x A-fragments ----
            uint32_t axh[8], axl[8];
#pragma unroll
            for (int kt = 0; kt < 2; kt++) {
                uint32_t o = (uint32_t)((warp * 16 + a_m) * ST32B + (kt * 16 + a_k) * 2);
                ldsm4(axh + kt * 4, smb + S_XH + o);
                ldsm4(axl + kt * 4, smb + S_XL + o);
            }

            // ---- layer 1: [16 x 32] x W0^T -> D[16 x 128] ----
            float d[64];
#pragma unroll
            for (int i = 0; i < 64; i++) d[i] = 0.f;
            gemm<2, 8, ST32B>(smb + S_W0H, smb + S_W0L, axh, axl, d, b_n, b_k);

            uint32_t acth[32], actl[32];
            epi128(d, sm, S_B0, acth, actl, lane);

            // ---- layer 2: [16 x 128] x W1^T -> D[16 x 128] ----
#pragma unroll
            for (int i = 0; i < 64; i++) d[i] = 0.f;
            gemm<8, 8, ST128B>(smb + S_W1H, smb + S_W1L, acth, actl, d, b_n, b_k);
            epi128(d, sm, S_B1, acth, actl, lane);

            // ---- layer 3: [16 x 128] x W2^T -> D3[16 x 16] ----
            float d3[8];
#pragma unroll
            for (int i = 0; i < 8; i++) d3[i] = 0.f;
            gemm<8, 1, ST128B>(smb + S_W2H, smb + S_W2L, acth, actl, d3, b_n, b_k);

            // ---- stage D3 to smem [row][16] ----
            {
                char* ob = sm + S_OUT + (size_t)(warp * 16) * 64;
                const int rlo = lane >> 2;
                const int c = (lane & 3) * 2;
#pragma unroll
                for (int tj = 0; tj < 2; tj++) {
                    *(float2*)(ob + rlo * 64 + (tj * 8 + c) * 4) =
                        make_float2(d3[tj * 4 + 0], d3[tj * 4 + 1]);
                    *(float2*)(ob + (rlo + 8) * 64 + (tj * 8 + c) * 4) =
                        make_float2(d3[tj * 4 + 2], d3[tj * 4 + 3]);
                }
            }
            __syncthreads();

            // ---- bias + expm + write ----
            if (tid < TB) {
                const float* orow_s = (const float*)(sm + S_OUT) + tid * 16;
                const float* b2s = (const float*)(sm + S_B2);
                float* og = out + (size_t)(r0 + tid) * 12 + (br ? 9 : 0);
                if (br == 0) {
                    float om[9], E[9];
#pragma unroll
                    for (int o = 0; o < 9; o++) om[o] = orow_s[o] + b2s[o];
                    expm3(om, E);
#pragma unroll
                    for (int o = 0; o < 9; o++) og[o] = E[o];
                } else {
#pragma unroll
                    for (int o = 0; o < 3; o++) og[o] = orow_s[o] + b2s[o];
                }
            }
            __syncthreads();
        }
    }
}

// ---------------- launch ----------------
extern "C" void kernel_launch(void* const* d_in, const int* in_sizes, int n_in,
                              void* d_out, int out_size) {
    const float* y   = (const float*)d_in[0];
    const float* ow0 = (const float*)d_in[1];
    const float* ob0 = (const float*)d_in[2];
    const float* ow1 = (const float*)d_in[3];
    const float* ob1 = (const float*)d_in[4];
    const float* ow2 = (const float*)d_in[5];
    const float* ob2 = (const float*)d_in[6];
    const float* tw0 = (const float*)d_in[7];
    const float* tb0 = (const float*)d_in[8];
    const float* tw1 = (const float*)d_in[9];
    const float* tb1 = (const float*)d_in[10];
    const float* tw2 = (const float*)d_in[11];
    const float* tb2 = (const float*)d_in[12];
    float* out = (float*)d_out;

    cudaFuncSetAttribute(fused_kernel,
                         cudaFuncAttributeMaxDynamicSharedMemorySize, SMEM_TOTAL);
    fused_kernel<<<GRID, NTHREADS, SMEM_TOTAL>>>(
        y, ow0, ob0, ow1, ob1, ow2, ob2, tw0, tb0, tw1, tb1, tw2, tb2, out);
}